// round 1
// baseline (speedup 1.0000x reference)
#include <cuda_runtime.h>
#include <cuda_bf16.h>

#define EPS 1e-6f
#define NCOLS 4096
#define MAXB  8192

// Per-row partials (deterministic two-pass reduction; no device allocation).
__device__ float g_pw[MAXB];   // sum over row of depth_weights * bce
__device__ int   g_ps[MAXB];   // max streak of the row

// One CTA per row. 256 threads x 16 contiguous elements (4 x float4 = 64B/thread/array).
__global__ __launch_bounds__(256)
void depth_loss_row_kernel(const float4* __restrict__ p4,
                           const float4* __restrict__ t4,
                           const float4* __restrict__ w4)
{
    const int row = blockIdx.x;
    const int tid = threadIdx.x;
    const int N4  = NCOLS / 4;                 // 1024 float4 per row
    size_t base = (size_t)row * N4 + (size_t)tid * 4;

    float wsum = 0.0f;
    int cur = 0, best = 0, pref = -1, k = 0;

#pragma unroll
    for (int i = 0; i < 4; i++) {
        float4 p = p4[base + i];
        float4 t = t4[base + i];
        float4 w = w4[base + i];
        float pp[4] = {p.x, p.y, p.z, p.w};
        float tt[4] = {t.x, t.y, t.z, t.w};
        float ww[4] = {w.x, w.y, w.z, w.w};
#pragma unroll
        for (int j = 0; j < 4; j++) {
            // y_true is exactly 0.0f or 1.0f -> single log per element
            float v = (tt[j] > 0.5f) ? (pp[j] + EPS) : (1.0f - pp[j] + EPS);
            wsum += ww[j] * (-__logf(v));
            float yb = (pp[j] > 0.5f) ? 1.0f : 0.0f;
            bool corr = (yb == tt[j]);
            if (corr) {
                cur++;
                best = (cur > best) ? cur : best;
            } else {
                if (pref < 0) pref = k;
                cur = 0;
            }
            k++;
        }
    }
    if (pref < 0) pref = 16;   // whole segment correct
    // leaf segment state: (prefix_run, suffix_run, best_run, len)
    __shared__ int4  s[256];
    __shared__ float sw[256];
    s[tid]  = make_int4(pref, cur, best, 16);
    sw[tid] = wsum;
    __syncthreads();

    // ordered tree combine: s[tid] covers [tid*16, (tid+stride)*16)
#pragma unroll
    for (int stride = 1; stride < 256; stride <<= 1) {
        if ((tid & (2 * stride - 1)) == 0) {
            int4 a = s[tid];
            int4 b = s[tid + stride];
            int4 c;
            c.w = a.w + b.w;                                  // len
            c.x = (a.x == a.w) ? (a.w + b.x) : a.x;           // prefix
            c.y = (b.y == b.w) ? (b.w + a.y) : b.y;           // suffix
            int cross = a.y + b.x;                            // run across the seam
            c.z = max(max(a.z, b.z), cross);                  // best
            s[tid]  = c;
            sw[tid] = sw[tid] + sw[tid + stride];
        }
        __syncthreads();
    }

    if (tid == 0) {
        g_pw[row] = sw[0];
        g_ps[row] = s[0].z;
    }
}

__global__ __launch_bounds__(256)
void depth_loss_reduce_kernel(float* __restrict__ out, int B)
{
    const int tid = threadIdx.x;
    double wsum = 0.0, ssum = 0.0;
    for (int i = tid; i < B; i += 256) {
        wsum += (double)g_pw[i];
        ssum += (double)g_ps[i];
    }
    __shared__ double dw[256];
    __shared__ double ds[256];
    dw[tid] = wsum;
    ds[tid] = ssum;
    __syncthreads();
    for (int st = 128; st > 0; st >>= 1) {
        if (tid < st) {
            dw[tid] += dw[tid + st];
            ds[tid] += ds[tid + st];
        }
        __syncthreads();
    }
    if (tid == 0) {
        double BN   = (double)B * (double)NCOLS;
        double wbce = dw[0] / BN;                 // mean(depth_weights * bce)
        double cwl  = 1.0 - ds[0] / BN;           // mean(1 - max_streak/N)
        out[0] = (float)(0.5 * wbce + 0.5 * cwl);
    }
}

extern "C" void kernel_launch(void* const* d_in, const int* in_sizes, int n_in,
                              void* d_out, int out_size)
{
    const float4* p4 = (const float4*)d_in[0];   // y_pred
    const float4* t4 = (const float4*)d_in[1];   // y_true
    const float4* w4 = (const float4*)d_in[2];   // depth_weights
    int total = in_sizes[0];
    int B = total / NCOLS;                       // 8192

    depth_loss_row_kernel<<<B, 256>>>(p4, t4, w4);
    depth_loss_reduce_kernel<<<1, 256>>>((float*)d_out, B);
}

// round 2
// speedup vs baseline: 1.7232x; 1.7232x over previous
#include <cuda_runtime.h>
#include <cuda_bf16.h>

#define EPS   1e-6f
#define NCOLS 4096
#define MAXB  8192

// Per-row partials + completion counter (no device allocation; graph-replay safe).
__device__ float g_pw[MAXB];       // sum over row of depth_weights * bce
__device__ int   g_ps[MAXB];       // max streak of the row
__device__ unsigned int g_count = 0;

// Segment-state combine: a (left, length la) ++ b (right, length lb).
__device__ __forceinline__ void seg_combine(int& ap, int& as, int& ab, int la,
                                            int bp, int bs, int bb, int lb)
{
    int np = (ap == la) ? la + bp : ap;     // prefix run
    int ns = (bs == lb) ? lb + as : bs;     // suffix run
    int nb = max(max(ab, bb), as + bp);     // best run (incl. seam)
    ap = np; as = ns; ab = nb;
}

// One CTA per row, 256 threads (8 warps). Warp w owns float4 [w*128, w*128+128).
// Lane i, iter j loads float4 (w*128 + j*32 + i)  -> stride-1 lane coalescing.
__global__ __launch_bounds__(256)
void depth_loss_fused_kernel(const float4* __restrict__ p4,
                             const float4* __restrict__ t4,
                             const float4* __restrict__ w4,
                             float* __restrict__ out, int B)
{
    const int row  = blockIdx.x;
    const int tid  = threadIdx.x;
    const int warp = tid >> 5;
    const int lane = tid & 31;
    const size_t wbase = (size_t)row * (NCOLS / 4) + warp * 128 + lane;

    float wsum = 0.0f;
    int Rp = 0, Rs = 0, Rb = 0;            // running warp state over j segments

#pragma unroll
    for (int j = 0; j < 4; j++) {
        size_t idx = wbase + j * 32;
        float4 p = __ldcs(&p4[idx]);
        float4 t = __ldcs(&t4[idx]);
        float4 w = __ldcs(&w4[idx]);

        float pp[4] = {p.x, p.y, p.z, p.w};
        float tt[4] = {t.x, t.y, t.z, t.w};
        float ww[4] = {w.x, w.y, w.z, w.w};

        // leaf state over this thread's 4 contiguous elements (branch-free)
        int cur = 0, best = 0, pref = 0, all = 1;
#pragma unroll
        for (int e = 0; e < 4; e++) {
            bool tb = (tt[e] > 0.5f);
            bool pb = (pp[e] > 0.5f);
            int corr = (tb == pb) ? 1 : 0;
            float v = tb ? (pp[e] + EPS) : ((1.0f - pp[e]) + EPS);
            wsum = fmaf(ww[e], -__logf(v), wsum);
            cur  = corr ? (cur + 1) : 0;
            best = max(best, cur);
            all &= corr;
            pref += all;
        }
        int suf = cur;

        // warp tree combine: 4-elem leaves -> 128-elem segment (valid in lane 0)
#pragma unroll
        for (int s = 0; s < 5; s++) {
            int len = 4 << s;
            int op = __shfl_down_sync(0xffffffffu, pref, 1 << s);
            int os = __shfl_down_sync(0xffffffffu, suf,  1 << s);
            int ob = __shfl_down_sync(0xffffffffu, best, 1 << s);
            seg_combine(pref, suf, best, len, op, os, ob, len);
        }
        pref = __shfl_sync(0xffffffffu, pref, 0);
        suf  = __shfl_sync(0xffffffffu, suf,  0);
        best = __shfl_sync(0xffffffffu, best, 0);

        // fold segment j (128 elems) into running state (128*j elems)
        if (j == 0) { Rp = pref; Rs = suf; Rb = best; }
        else        { seg_combine(Rp, Rs, Rb, 128 * j, pref, suf, best, 128); }
    }

    // warp wsum reduce
#pragma unroll
    for (int s = 16; s > 0; s >>= 1)
        wsum += __shfl_down_sync(0xffffffffu, wsum, s);

    __shared__ int   shp[8], shs[8], shb[8];
    __shared__ float shw[8];
    __shared__ int   s_isLast;
    if (lane == 0) { shp[warp] = Rp; shs[warp] = Rs; shb[warp] = Rb; shw[warp] = wsum; }
    __syncthreads();

    if (tid == 0) {
        int ap = shp[0], as = shs[0], ab = shb[0];
        float ws = shw[0];
#pragma unroll
        for (int w = 1; w < 8; w++) {
            seg_combine(ap, as, ab, 512 * w, shp[w], shs[w], shb[w], 512);
            ws += shw[w];
        }
        g_pw[row] = ws;
        g_ps[row] = ab;
        __threadfence();
        unsigned int done = atomicAdd(&g_count, 1u);
        s_isLast = (done == (unsigned int)(gridDim.x - 1)) ? 1 : 0;
    }
    __syncthreads();

    if (s_isLast) {
        __threadfence();   // acquire: see all rows' partials
        // 256 threads x 32 rows, unrolled x4 for MLP
        double dw = 0.0;
        long long dsi = 0;
        for (int r = tid; r < B; r += 1024) {
            float  a0 = g_pw[r], a1 = g_pw[r + 256], a2 = g_pw[r + 512], a3 = g_pw[r + 768];
            int    b0 = g_ps[r], b1 = g_ps[r + 256], b2 = g_ps[r + 512], b3 = g_ps[r + 768];
            dw  += (double)a0 + (double)a1 + (double)a2 + (double)a3;
            dsi += (long long)b0 + b1 + b2 + b3;
        }
        __shared__ double    rdw[256];
        __shared__ long long rds[256];
        rdw[tid] = dw;
        rds[tid] = dsi;
        __syncthreads();
#pragma unroll
        for (int st = 128; st > 0; st >>= 1) {
            if (tid < st) { rdw[tid] += rdw[tid + st]; rds[tid] += rds[tid + st]; }
            __syncthreads();
        }
        if (tid == 0) {
            double BN   = (double)B * (double)NCOLS;
            double wbce = rdw[0] / BN;                       // mean(w * bce)
            double cwl  = 1.0 - ((double)rds[0]) / BN;       // mean(1 - streak/N)
            out[0] = (float)(0.5 * wbce + 0.5 * cwl);
            g_count = 0;                                     // reset for next replay
        }
    }
}

extern "C" void kernel_launch(void* const* d_in, const int* in_sizes, int n_in,
                              void* d_out, int out_size)
{
    const float4* p4 = (const float4*)d_in[0];   // y_pred
    const float4* t4 = (const float4*)d_in[1];   // y_true
    const float4* w4 = (const float4*)d_in[2];   // depth_weights
    int total = in_sizes[0];
    int B = total / NCOLS;                       // 8192

    depth_loss_fused_kernel<<<B, 256>>>(p4, t4, w4, (float*)d_out, B);
}

// round 3
// speedup vs baseline: 1.7706x; 1.0275x over previous
#include <cuda_runtime.h>
#include <cuda_bf16.h>

#define EPS   1e-6f
#define NCOLS 4096
#define MAXB  8192

// Per-row partials + completion counter (no device allocation; graph-replay safe).
__device__ float g_pw[MAXB];       // sum over row of depth_weights * bce
__device__ int   g_ps[MAXB];       // max streak of the row
__device__ unsigned int g_count = 0;

// Packed segment state: pref | suf<<10 | best<<20  (each <= 512, fits 10 bits)
__device__ __forceinline__ unsigned pack3(int p, int s, int b) {
    return (unsigned)p | ((unsigned)s << 10) | ((unsigned)b << 20);
}

// Combine left segment a (length la) with right segment b (length lb).
__device__ __forceinline__ unsigned seg_combine(unsigned a, int la, unsigned b, int lb)
{
    int ap = a & 1023, as = (a >> 10) & 1023, ab = (int)(a >> 20);
    int bp = b & 1023, bs = (b >> 10) & 1023, bb = (int)(b >> 20);
    int np = (ap == la) ? la + bp : ap;          // prefix run
    int ns = (bs == lb) ? lb + as : bs;          // suffix run
    int nb = max(max(ab, bb), as + bp);          // best run (incl. seam)
    return pack3(np, ns, nb);
}

// One CTA per row, 256 threads (8 warps). Warp w owns float4 [w*128, (w+1)*128).
// Lane i, iter j loads float4 (w*128 + j*32 + i)  -> stride-1 lane coalescing.
__global__ __launch_bounds__(256, 6)
void depth_loss_fused_kernel(const float4* __restrict__ p4,
                             const float4* __restrict__ t4,
                             const float4* __restrict__ w4,
                             float* __restrict__ out, int B)
{
    const int row  = blockIdx.x;
    const int tid  = threadIdx.x;
    const int warp = tid >> 5;
    const int lane = tid & 31;
    const size_t wbase = (size_t)row * (NCOLS / 4) + warp * 128 + lane;

    float wsum = 0.0f;
    unsigned R = 0;                        // running warp state (valid in lane 0)

    // software pipeline: prefetch iteration 0
    float4 p = __ldcs(&p4[wbase]);
    float4 t = __ldcs(&t4[wbase]);
    float4 w = __ldcs(&w4[wbase]);

#pragma unroll
    for (int j = 0; j < 4; j++) {
        float4 pn, tn, wn;
        if (j < 3) {
            size_t nidx = wbase + (size_t)(j + 1) * 32;
            pn = __ldcs(&p4[nidx]);
            tn = __ldcs(&t4[nidx]);
            wn = __ldcs(&w4[nidx]);
        }

        float pp[4] = {p.x, p.y, p.z, p.w};
        float tt[4] = {t.x, t.y, t.z, t.w};
        float ww[4] = {w.x, w.y, w.z, w.w};

        // leaf state over this thread's 4 contiguous elements (branch-free)
        int cur = 0, best = 0, pref = 0, all = 1;
#pragma unroll
        for (int e = 0; e < 4; e++) {
            bool tb = (tt[e] > 0.5f);
            bool pb = (pp[e] > 0.5f);
            int corr = (tb == pb) ? 1 : 0;
            float v = tb ? (pp[e] + EPS) : ((1.0f - pp[e]) + EPS);
            wsum = fmaf(ww[e], -__logf(v), wsum);
            cur  = corr ? (cur + 1) : 0;
            best = max(best, cur);
            all &= corr;
            pref += all;
        }
        unsigned seg = pack3(pref, cur, best);

        // warp tree combine: 4-elem leaves -> 128-elem segment (valid in lane 0)
#pragma unroll
        for (int s = 0; s < 5; s++) {
            unsigned o = __shfl_down_sync(0xffffffffu, seg, 1 << s);
            seg = seg_combine(seg, 4 << s, o, 4 << s);
        }

        // fold segment j (128 elems) into running state; only lane 0 meaningful
        R = (j == 0) ? seg : seg_combine(R, 128 * j, seg, 128);

        p = pn; t = tn; w = wn;
    }

    // warp wsum reduce
#pragma unroll
    for (int s = 16; s > 0; s >>= 1)
        wsum += __shfl_down_sync(0xffffffffu, wsum, s);

    __shared__ unsigned shseg[8];
    __shared__ float    shw[8];
    __shared__ int      s_isLast;
    if (lane == 0) { shseg[warp] = R; shw[warp] = wsum; }
    __syncthreads();

    if (tid == 0) {
        unsigned a = shseg[0];
        float ws = shw[0];
#pragma unroll
        for (int wi = 1; wi < 8; wi++) {
            a = seg_combine(a, 512 * wi, shseg[wi], 512);
            ws += shw[wi];
        }
        g_pw[row] = ws;
        g_ps[row] = (int)(a >> 20);
        __threadfence();
        unsigned int done = atomicAdd(&g_count, 1u);
        s_isLast = (done == (unsigned int)(gridDim.x - 1)) ? 1 : 0;
    }
    __syncthreads();

    if (s_isLast) {
        __threadfence();   // acquire: see all rows' partials
        double dw = 0.0;
        long long dsi = 0;
        for (int r = tid; r < B; r += 1024) {
            float  a0 = g_pw[r], a1 = g_pw[r + 256], a2 = g_pw[r + 512], a3 = g_pw[r + 768];
            int    b0 = g_ps[r], b1 = g_ps[r + 256], b2 = g_ps[r + 512], b3 = g_ps[r + 768];
            dw  += (double)a0 + (double)a1 + (double)a2 + (double)a3;
            dsi += (long long)b0 + b1 + b2 + b3;
        }
        __shared__ double    rdw[256];
        __shared__ long long rds[256];
        rdw[tid] = dw;
        rds[tid] = dsi;
        __syncthreads();
#pragma unroll
        for (int st = 128; st > 0; st >>= 1) {
            if (tid < st) { rdw[tid] += rdw[tid + st]; rds[tid] += rds[tid + st]; }
            __syncthreads();
        }
        if (tid == 0) {
            double BN   = (double)B * (double)NCOLS;
            double wbce = rdw[0] / BN;                       // mean(w * bce)
            double cwl  = 1.0 - ((double)rds[0]) / BN;       // mean(1 - streak/N)
            out[0] = (float)(0.5 * wbce + 0.5 * cwl);
            g_count = 0;                                     // reset for next replay
        }
    }
}

extern "C" void kernel_launch(void* const* d_in, const int* in_sizes, int n_in,
                              void* d_out, int out_size)
{
    const float4* p4 = (const float4*)d_in[0];   // y_pred
    const float4* t4 = (const float4*)d_in[1];   // y_true
    const float4* w4 = (const float4*)d_in[2];   // depth_weights
    int total = in_sizes[0];
    int B = total / NCOLS;                       // 8192

    depth_loss_fused_kernel<<<B, 256>>>(p4, t4, w4, (float*)d_out, B);
}

// round 5
// speedup vs baseline: 1.9370x; 1.0940x over previous
#include <cuda_runtime.h>
#include <cuda_bf16.h>

#define EPS   1e-6f
#define NCOLS 4096
#define MAXB  8192

// Per-row partials + completion counter (no device allocation; graph-replay safe).
__device__ float g_pw[MAXB];       // sum over row of depth_weights * bce
__device__ int   g_ps[MAXB];       // max streak of the row
__device__ unsigned int g_count = 0;

// Combine left (ap,as,ab | len la) with right (bp,bs,bb | len lb); result in a*.
#define SEG_COMBINE(ap, as, ab, la, bp, bs, bb, lb)              \
    do {                                                         \
        int _np = ((ap) == (la)) ? (la) + (bp) : (ap);           \
        int _ns = ((bs) == (lb)) ? (lb) + (as) : (bs);           \
        int _nb = max(max((ab), (bb)), (as) + (bp));             \
        (ap) = _np; (as) = _ns; (ab) = _nb;                      \
    } while (0)

// One CTA per row, 256 threads (8 warps). Warp w owns float4 [w*128, (w+1)*128).
// Lane i, iter j loads float4s (w*128 + j*64 + 2i, +1): 8 contiguous elements
// per thread per iteration -> 8-elem leaves, only 2 warp trees per thread.
__global__ __launch_bounds__(256, 5)
void depth_loss_fused_kernel(const float4* __restrict__ p4,
                             const float4* __restrict__ t4,
                             const float4* __restrict__ w4,
                             float* __restrict__ out, int B)
{
    const int row  = blockIdx.x;
    const int tid  = threadIdx.x;
    const int warp = tid >> 5;
    const int lane = tid & 31;
    const size_t wbase = (size_t)row * (NCOLS / 4) + warp * 128 + lane * 2;

    float wsum = 0.0f;
    int Rp = 0, Rs = 0, Rb = 0;     // running warp state (valid in lane 0)

    // software pipeline: prefetch iteration 0 (two float4 per array)
    float4 pA = __ldcs(&p4[wbase]),     pB = __ldcs(&p4[wbase + 1]);
    float4 tA = __ldcs(&t4[wbase]),     tB = __ldcs(&t4[wbase + 1]);
    float4 wA = __ldcs(&w4[wbase]),     wB = __ldcs(&w4[wbase + 1]);

#pragma unroll
    for (int j = 0; j < 2; j++) {
        float4 pAn, pBn, tAn, tBn, wAn, wBn;
        if (j == 0) {
            size_t nidx = wbase + 64;
            pAn = __ldcs(&p4[nidx]); pBn = __ldcs(&p4[nidx + 1]);
            tAn = __ldcs(&t4[nidx]); tBn = __ldcs(&t4[nidx + 1]);
            wAn = __ldcs(&w4[nidx]); wBn = __ldcs(&w4[nidx + 1]);
        }

        float pp[8] = {pA.x, pA.y, pA.z, pA.w, pB.x, pB.y, pB.z, pB.w};
        float tt[8] = {tA.x, tA.y, tA.z, tA.w, tB.x, tB.y, tB.z, tB.w};
        float ww[8] = {wA.x, wA.y, wA.z, wA.w, wB.x, wB.y, wB.z, wB.w};

        // leaf state over this thread's 8 contiguous elements (branch-free)
        int cur = 0, best = 0, pref = 0, all = 1;
#pragma unroll
        for (int e = 0; e < 8; e++) {
            bool tb = (tt[e] > 0.5f);
            bool pb = (pp[e] > 0.5f);
            int corr = (tb == pb) ? 1 : 0;
            float v = tb ? (pp[e] + EPS) : ((1.0f - pp[e]) + EPS);
            wsum = fmaf(ww[e], -__logf(v), wsum);
            cur  = corr ? (cur + 1) : 0;
            best = max(best, cur);
            all &= corr;
            pref += all;
        }
        int suf = cur;

        // warp tree: 8-elem leaves -> 256-elem segment (valid in lane 0)
#pragma unroll
        for (int s = 0; s < 5; s++) {
            int len = 8 << s;
            int op = __shfl_down_sync(0xffffffffu, pref, 1 << s);
            int os = __shfl_down_sync(0xffffffffu, suf,  1 << s);
            int ob = __shfl_down_sync(0xffffffffu, best, 1 << s);
            SEG_COMBINE(pref, suf, best, len, op, os, ob, len);
        }

        // fold segment j (256 elems) into running state
        if (j == 0) { Rp = pref; Rs = suf; Rb = best; }
        else        { SEG_COMBINE(Rp, Rs, Rb, 256, pref, suf, best, 256); }

        pA = pAn; pB = pBn; tA = tAn; tB = tBn; wA = wAn; wB = wBn;
    }

    // warp wsum reduce
#pragma unroll
    for (int s = 16; s > 0; s >>= 1)
        wsum += __shfl_down_sync(0xffffffffu, wsum, s);

    __shared__ int   shp[8], shs[8], shb[8];
    __shared__ float shw[8];
    __shared__ int   s_isLast;
    if (lane == 0) { shp[warp] = Rp; shs[warp] = Rs; shb[warp] = Rb; shw[warp] = wsum; }
    __syncthreads();

    if (tid == 0) {
        int ap = shp[0], as = shs[0], ab = shb[0];
        float ws = shw[0];
#pragma unroll
        for (int wi = 1; wi < 8; wi++) {
            SEG_COMBINE(ap, as, ab, 512 * wi, shp[wi], shs[wi], shb[wi], 512);
            ws += shw[wi];
        }
        g_pw[row] = ws;
        g_ps[row] = ab;
        __threadfence();
        unsigned int done = atomicAdd(&g_count, 1u);
        s_isLast = (done == (unsigned int)(gridDim.x - 1)) ? 1 : 0;
    }
    __syncthreads();

    if (s_isLast) {
        __threadfence();   // acquire: see all rows' partials
        double dw = 0.0;
        long long dsi = 0;
        for (int r = tid; r < B; r += 1024) {
            float  a0 = g_pw[r], a1 = g_pw[r + 256], a2 = g_pw[r + 512], a3 = g_pw[r + 768];
            int    b0 = g_ps[r], b1 = g_ps[r + 256], b2 = g_ps[r + 512], b3 = g_ps[r + 768];
            dw  += (double)a0 + (double)a1 + (double)a2 + (double)a3;
            dsi += (long long)b0 + b1 + b2 + b3;
        }
        __shared__ double    rdw[256];
        __shared__ long long rds[256];
        rdw[tid] = dw;
        rds[tid] = dsi;
        __syncthreads();
#pragma unroll
        for (int st = 128; st > 0; st >>= 1) {
            if (tid < st) { rdw[tid] += rdw[tid + st]; rds[tid] += rds[tid + st]; }
            __syncthreads();
        }
        if (tid == 0) {
            double BN   = (double)B * (double)NCOLS;
            double wbce = rdw[0] / BN;                       // mean(w * bce)
            double cwl  = 1.0 - ((double)rds[0]) / BN;       // mean(1 - streak/N)
            out[0] = (float)(0.5 * wbce + 0.5 * cwl);
            g_count = 0;                                     // reset for next replay
        }
    }
}

extern "C" void kernel_launch(void* const* d_in, const int* in_sizes, int n_in,
                              void* d_out, int out_size)
{
    const float4* p4 = (const float4*)d_in[0];   // y_pred
    const float4* t4 = (const float4*)d_in[1];   // y_true
    const float4* w4 = (const float4*)d_in[2];   // depth_weights
    int total = in_sizes[0];
    int B = total / NCOLS;                       // 8192

    depth_loss_fused_kernel<<<B, 256>>>(p4, t4, w4, (float*)d_out, B);
}